// round 9
// baseline (speedup 1.0000x reference)
#include <cuda_runtime.h>
#include <cuda_fp16.h>
#include <cstdint>

// TwoBranchDH_SFNN, R8: instruction-count surgery.
// grid=128 (block per batch), 768 threads (24 warps):
//   warps  0-7  ("compute"): recurrence 2ch/thread (f32x2-packed) + ysum (2 t/warp)
//   warps  8-23 ("mma"):     x staging + ldmatrix + HMMA + float4 dot stores
// Dot layout: dot[buf][br][tlo][chpair] as float4 = (ch,ch+1)@t, (ch,ch+1)@t+8.
// One __syncthreads per 16-timestep stage; dots / y / x double-buffered.

namespace {

constexpr int B_SZ  = 128;
constexpr int T_SZ  = 2048;
constexpr int DIN   = 40;
constexpr int KHALF = 20;
constexpr int THREADS = 768;
constexpr int ST      = 16;             // timesteps per stage
constexpr int NSTAGES = T_SZ / ST;      // 128

// smem geometry (32-bit words)
constexpr int ROWW = 1040;              // dot row stride (256 chpair * 4 + pad; ≡16 mod 32)
constexpr int BRW2 = 8 * ROWW;          // per-branch words (8 tlo rows)
constexpr int DOTB = 2 * BRW2;          // both branches, one buffer = 16640
constexpr int YW2  = 260;               // y row stride (256 + pad)
constexpr int YT2  = ST * YW2;          // one y buffer = 4160
constexpr int XWH  = 1024;              // halves per x buffer (16 t x 64)
constexpr int SMEM_BYTES = (2 * DOTB + 2 * YT2) * 4 + 2 * XWH * 2;  // 170496 B

typedef unsigned long long u64;
typedef uint32_t u32;

__device__ __forceinline__ u32 smem_u32(const void* p) {
    u32 a;
    asm("{ .reg .u64 t; cvta.to.shared.u64 t, %1; cvt.u32.u64 %0, t; }"
        : "=r"(a) : "l"(p));
    return a;
}
__device__ __forceinline__ u64 pkf(float lo, float hi) {
    u64 r; asm("mov.b64 %0, {%1, %2};" : "=l"(r) : "f"(lo), "f"(hi)); return r;
}
__device__ __forceinline__ float2 unpk(u64 v) {
    float2 r; asm("mov.b64 {%0, %1}, %2;" : "=f"(r.x), "=f"(r.y) : "l"(v)); return r;
}
__device__ __forceinline__ u64 fma2(u64 a, u64 b, u64 c) {
    u64 d; asm("fma.rn.f32x2 %0, %1, %2, %3;" : "=l"(d) : "l"(a), "l"(b), "l"(c)); return d;
}
__device__ __forceinline__ u64 add2(u64 a, u64 b) {
    u64 d; asm("add.rn.f32x2 %0, %1, %2;" : "=l"(d) : "l"(a), "l"(b)); return d;
}
__device__ __forceinline__ u64 mul2(u64 a, u64 b) {
    u64 d; asm("mul.rn.f32x2 %0, %1, %2;" : "=l"(d) : "l"(a), "l"(b)); return d;
}

__device__ __forceinline__ void ldmat4(u32* r, u32 addr) {
    asm volatile("ldmatrix.sync.aligned.m8n8.x4.shared.b16 {%0,%1,%2,%3}, [%4];"
                 : "=r"(r[0]), "=r"(r[1]), "=r"(r[2]), "=r"(r[3]) : "r"(addr));
}
__device__ __forceinline__ void mma16816(float& d0, float& d1, float& d2, float& d3,
                                         const u32* a, u32 b0, u32 b1) {
    asm volatile("mma.sync.aligned.m16n8k16.row.col.f32.f16.f16.f32 "
                 "{%0,%1,%2,%3}, {%4,%5,%6,%7}, {%8,%9}, {%0,%1,%2,%3};"
                 : "+f"(d0), "+f"(d1), "+f"(d2), "+f"(d3)
                 : "r"(a[0]), "r"(a[1]), "r"(a[2]), "r"(a[3]), "r"(b0), "r"(b1));
}
__device__ __forceinline__ float sigf(float v) { return 1.0f / (1.0f + expf(-v)); }
__device__ __forceinline__ u32 packh(float a, float b) {
    __half2 h = __floats2half2_rn(a, b);
    return *reinterpret_cast<u32*>(&h);
}

__global__ void __launch_bounds__(THREADS, 1)
sfnn_r8_kernel(const float* __restrict__ x,
               const float* __restrict__ W1, const float* __restrict__ b1,
               const float* __restrict__ W2, const float* __restrict__ b2,
               const float* __restrict__ Wo, const float* __restrict__ bo,
               const float* __restrict__ tau_m, const float* __restrict__ tau_n1,
               const float* __restrict__ tau_n2, float* __restrict__ out) {
    extern __shared__ __align__(16) float sm[];
    float* dotsm = sm;                                   // 2*DOTB words
    float* ysm   = sm + 2 * DOTB;                        // 2*YT2 words
    __half* xsm  = reinterpret_cast<__half*>(sm + 2 * DOTB + 2 * YT2);

    const int tid  = threadIdx.x;
    const int lane = tid & 31;
    const int wid  = tid >> 5;
    const int b    = blockIdx.x;
    const bool is_mma = (wid >= 8);

    const float* xg = x + (size_t)b * T_SZ * DIN;
    const u32 xbase = smem_u32(xsm);
    float* ob = out + (size_t)b * T_SZ;

    // ================= compute-role constants (2 channels h0,h1) ============
    u64 B1p = 0, G1p = 0, GB1p = 0, B2p = 0, G2p = 0, GB2p = 0;
    u64 ALp = 0, AMp = 0, WOp = 0;
    float bov = 0.f;
    if (!is_mma) {
        const int h0 = 2 * tid, h1 = h0 + 1;
        const float b1a = sigf(tau_n1[h0]), b1b = sigf(tau_n1[h1]);
        const float b2a = sigf(tau_n2[h0]), b2b = sigf(tau_n2[h1]);
        const float ala = sigf(tau_m[h0]),  alb = sigf(tau_m[h1]);
        B1p  = pkf(b1a, b1b);
        G1p  = pkf(1.f - b1a, 1.f - b1b);
        GB1p = pkf((1.f - b1a) * b1[h0], (1.f - b1b) * b1[h1]);
        B2p  = pkf(b2a, b2b);
        G2p  = pkf(1.f - b2a, 1.f - b2b);
        GB2p = pkf((1.f - b2a) * b2[h0], (1.f - b2b) * b2[h1]);
        ALp  = pkf(ala, alb);
        AMp  = pkf(1.f - ala, 1.f - alb);
        WOp  = pkf(Wo[h0], Wo[h1]);
        bov  = bo[0];
    }

    // ================= mma-role constants ================================
    const int wid2 = wid - 8;                   // 0..15
    const int wbr  = (wid2 >> 3) & 1;           // branch
    const int wb   = (wid2 & 7) * 64;           // channel base
    u32 BF[8][2][2];
    if (is_mma) {
        const float* Ws = wbr ? W2 : W1;
        const int chl = lane >> 2;
        const int kg  = 2 * (lane & 3);
#pragma unroll
        for (int nt = 0; nt < 8; nt++) {
            const int ch = wb + nt * 8 + chl;
#pragma unroll
            for (int kt = 0; kt < 2; kt++) {
                const int k0 = kt * 16 + kg;
                const float v0 = (k0     < KHALF) ? Ws[ch * KHALF + k0    ] : 0.f;
                const float v1 = (k0 + 1 < KHALF) ? Ws[ch * KHALF + k0 + 1] : 0.f;
                const float v2 = (k0 + 8 < KHALF) ? Ws[ch * KHALF + k0 + 8] : 0.f;
                const float v3 = (k0 + 9 < KHALF) ? Ws[ch * KHALF + k0 + 9] : 0.f;
                BF[nt][kt][0] = packh(v0, v1);
                BF[nt][kt][1] = packh(v2, v3);
            }
        }
    }

    // x staging slots: 512 mma threads, 1024 slots, 2 each
    const int tid2 = tid - 256;                 // 0..511 for mma threads
    int xsl_t[2], xsl_kk[2], xsl_g[2]; bool xsl_ok[2];
    if (is_mma) {
#pragma unroll
        for (int i = 0; i < 2; i++) {
            const int sl = tid2 + i * 512;
            const int t = sl >> 6, kk = sl & 63, br = kk >> 5, k = kk & 31;
            xsl_t[i] = t; xsl_kk[i] = kk;
            xsl_ok[i] = (k < KHALF);
            xsl_g[i] = t * DIN + br * KHALF + k;
        }
    }

    // lane constants for dot store
    const int tlo = lane >> 2;                  // 0..7
    const int chp = wb / 2 + (lane & 3);        // + nt*4 inside loop

    auto mma_stage = [&](int s) {
        const int buf = s & 1;
        u32 A[2][4];
#pragma unroll
        for (int kt = 0; kt < 2; kt++) {
            const u32 addr = xbase + (u32)buf * (XWH * 2)
                           + (u32)(lane & 15) * 128
                           + (u32)(wbr * 32 + kt * 16 + ((lane >> 4) << 3)) * 2;
            ldmat4(A[kt], addr);
        }
        float* dB = dotsm + buf * DOTB + wbr * BRW2 + tlo * ROWW;
#pragma unroll
        for (int nt = 0; nt < 8; nt++) {
            float d0 = 0.f, d1 = 0.f, d2 = 0.f, d3 = 0.f;
            mma16816(d0, d1, d2, d3, A[0], BF[nt][0][0], BF[nt][0][1]);
            mma16816(d0, d1, d2, d3, A[1], BF[nt][1][0], BF[nt][1][1]);
            *reinterpret_cast<float4*>(dB + (chp + nt * 4) * 4) =
                make_float4(d0, d1, d2, d3);
        }
    };

    auto ysum = [&](int s) {
        const float* yb = ysm + (s & 1) * YT2;
#pragma unroll
        for (int tt = 0; tt < 2; tt++) {
            const int t = wid * 2 + tt;
            const float4* yr = reinterpret_cast<const float4*>(yb + t * YW2);
            const float4 q0 = yr[lane];
            const float4 q1 = yr[lane + 32];
            float acc = ((q0.x + q0.y) + (q0.z + q0.w))
                      + ((q1.x + q1.y) + (q1.z + q1.w));
#pragma unroll
            for (int off = 16; off; off >>= 1)
                acc += __shfl_xor_sync(0xFFFFFFFFu, acc, off);
            if (lane == 0)
                ob[s * ST + t] = 1.f / (1.f + __expf(-(acc + bov)));
        }
    };

    // recurrence state (channel-pair packed)
    u64 d1p = 0ull, d2p = 0ull, memp = 0ull;

    auto step = [&](float* yb, int t, u64 i1p, u64 i2p) {
        d1p = fma2(B1p, d1p, fma2(G1p, i1p, GB1p));
        d2p = fma2(B2p, d2p, fma2(G2p, i2p, GB2p));
        memp = fma2(ALp, memp, mul2(AMp, add2(d1p, d2p)));
        const float2 yv = unpk(mul2(WOp, memp));
        yb[t * YW2 + tid] = yv.x + yv.y;
    };

    // ---- prolog: mma warps stage x(0), x(1); first MMA ----
    if (is_mma) {
#pragma unroll
        for (int ss = 0; ss < 2; ss++) {
            float v0 = xsl_ok[0] ? xg[ss * (ST * DIN) + xsl_g[0]] : 0.f;
            float v1 = xsl_ok[1] ? xg[ss * (ST * DIN) + xsl_g[1]] : 0.f;
            xsm[ss * XWH + xsl_t[0] * 64 + xsl_kk[0]] = __float2half_rn(v0);
            xsm[ss * XWH + xsl_t[1] * 64 + xsl_kk[1]] = __float2half_rn(v1);
        }
    }
    __syncthreads();
    if (is_mma) mma_stage(0);

    // ---- main loop: ONE barrier per stage ----
    for (int s = 0; s < NSTAGES; s++) {
        __syncthreads();   // dots(s), y(s-1), xbuf(s+1) visible

        if (is_mma) {
            // LDG for x(s+2) first (hide latency behind MMAs)
            float v0 = 0.f, v1 = 0.f;
            const bool dox = (s + 2 < NSTAGES);
            if (dox) {
                const size_t gb = (size_t)(s + 2) * (ST * DIN);
                v0 = xsl_ok[0] ? xg[gb + xsl_g[0]] : 0.f;
                v1 = xsl_ok[1] ? xg[gb + xsl_g[1]] : 0.f;
            }
            if (s + 1 < NSTAGES) mma_stage(s + 1);
            if (dox) {
                __half* xb = xsm + (s & 1) * XWH;   // (s+2)&1 == s&1
                xb[xsl_t[0] * 64 + xsl_kk[0]] = __float2half_rn(v0);
                xb[xsl_t[1] * 64 + xsl_kk[1]] = __float2half_rn(v1);
            }
        } else {
            if (s > 0) ysum(s - 1);
            // recurrence(s): dots buf s&1 -> y buf s&1
            const float* dB = dotsm + (s & 1) * DOTB;
            const float4* p1 = reinterpret_cast<const float4*>(dB + tid * 4);
            const float4* p2 = reinterpret_cast<const float4*>(dB + BRW2 + tid * 4);
            float* yb = ysm + (s & 1) * YT2;
            float zw[8][4];
#pragma unroll
            for (int r = 0; r < 8; r++) {
                const float4 a = p1[r * (ROWW / 4)];
                const float4 c = p2[r * (ROWW / 4)];
                step(yb, r, pkf(a.x, a.y), pkf(c.x, c.y));
                zw[r][0] = a.z; zw[r][1] = a.w;
                zw[r][2] = c.z; zw[r][3] = c.w;
            }
#pragma unroll
            for (int r = 0; r < 8; r++)
                step(yb, 8 + r, pkf(zw[r][0], zw[r][1]), pkf(zw[r][2], zw[r][3]));
        }
    }

    __syncthreads();
    if (!is_mma) ysum(NSTAGES - 1);
}

}  // namespace

extern "C" void kernel_launch(void* const* d_in, const int* in_sizes, int n_in,
                              void* d_out, int out_size) {
    const float* x      = (const float*)d_in[0];
    const float* W1     = (const float*)d_in[1];
    const float* b1     = (const float*)d_in[2];
    const float* W2     = (const float*)d_in[3];
    const float* b2     = (const float*)d_in[4];
    const float* Wo     = (const float*)d_in[5];
    const float* bo     = (const float*)d_in[6];
    const float* tau_m  = (const float*)d_in[7];
    const float* tau_n1 = (const float*)d_in[8];
    const float* tau_n2 = (const float*)d_in[9];
    float* out = (float*)d_out;

    cudaFuncSetAttribute(sfnn_r8_kernel,
                         cudaFuncAttributeMaxDynamicSharedMemorySize, SMEM_BYTES);
    sfnn_r8_kernel<<<B_SZ, THREADS, SMEM_BYTES>>>(x, W1, b1, W2, b2, Wo, bo,
                                                  tau_m, tau_n1, tau_n2, out);
}

// round 11
// speedup vs baseline: 2.4175x; 2.4175x over previous
#include <cuda_runtime.h>
#include <cuda_fp16.h>
#include <cstdint>

// TwoBranchDH_SFNN, R9: 2-way channel split -> 2 co-resident CTAs per SM.
// grid=256: block (half,b) owns channels [half*256, half*256+256) of batch b.
// Block = 256 threads (8 warps), R6-style combined roles:
//   MMA: warp w: branch = w>>2, 64-channel slice = (w&3)*64; ldmatrix+HMMA+STS
//   recurrence: thread tid <-> local channel tid (global hb+tid), f32x2 state
//   ysum: partial sum over the block's 256 channels -> g_part scratch
// Epilogue kernel: out = sigmoid(g_part[0]+g_part[1]+bo).
// One __syncthreads per 16-t stage; dots / y / x double-buffered. ~104KB smem.

namespace {

constexpr int B_SZ  = 128;
constexpr int T_SZ  = 2048;
constexpr int DIN   = 40;
constexpr int KHALF = 20;
constexpr int HB      = 256;            // channels per block
constexpr int THREADS = 256;
constexpr int ST      = 16;             // timesteps per stage
constexpr int NSTAGES = T_SZ / ST;      // 128

// smem geometry (32-bit words)
constexpr int TCW  = HB * 4 + 4;        // words per tc-slab (4 t x 256 ch + pad) = 1028
constexpr int BRW  = 4 * TCW;           // per-branch dot words = 4112
constexpr int DOTW = 2 * BRW;           // both branches, one buffer = 8224
constexpr int YW   = HB + 8;            // y row stride = 264
constexpr int YTOT = ST * YW;           // one y buffer = 4224
constexpr int XWH  = ST * 64;           // halves per x buffer = 1024
constexpr int SMEM_BYTES = (2 * DOTW + 2 * YTOT) * 4 + 2 * XWH * 2;  // 103680 B

typedef unsigned long long u64;
typedef uint32_t u32;

__device__ float g_part[2 * B_SZ * T_SZ];   // partial channel sums (2 MB)

__device__ __forceinline__ u32 smem_u32(const void* p) {
    u32 a;
    asm("{ .reg .u64 t; cvta.to.shared.u64 t, %1; cvt.u32.u64 %0, t; }"
        : "=r"(a) : "l"(p));
    return a;
}
__device__ __forceinline__ u64 pkf(float lo, float hi) {
    u64 r; asm("mov.b64 %0, {%1, %2};" : "=l"(r) : "f"(lo), "f"(hi)); return r;
}
__device__ __forceinline__ float2 unpk(u64 v) {
    float2 r; asm("mov.b64 {%0, %1}, %2;" : "=f"(r.x), "=f"(r.y) : "l"(v)); return r;
}
__device__ __forceinline__ u64 fma2(u64 a, u64 b, u64 c) {
    u64 d; asm("fma.rn.f32x2 %0, %1, %2, %3;" : "=l"(d) : "l"(a), "l"(b), "l"(c)); return d;
}

__device__ __forceinline__ void ldmat4(u32* r, u32 addr) {
    asm volatile("ldmatrix.sync.aligned.m8n8.x4.shared.b16 {%0,%1,%2,%3}, [%4];"
                 : "=r"(r[0]), "=r"(r[1]), "=r"(r[2]), "=r"(r[3]) : "r"(addr));
}
__device__ __forceinline__ void mma16816(float& d0, float& d1, float& d2, float& d3,
                                         const u32* a, u32 b0, u32 b1) {
    asm volatile("mma.sync.aligned.m16n8k16.row.col.f32.f16.f16.f32 "
                 "{%0,%1,%2,%3}, {%4,%5,%6,%7}, {%8,%9}, {%0,%1,%2,%3};"
                 : "+f"(d0), "+f"(d1), "+f"(d2), "+f"(d3)
                 : "r"(a[0]), "r"(a[1]), "r"(a[2]), "r"(a[3]), "r"(b0), "r"(b1));
}
__device__ __forceinline__ float sigf(float v) { return 1.0f / (1.0f + expf(-v)); }
__device__ __forceinline__ u32 packh(float a, float b) {
    __half2 h = __floats2half2_rn(a, b);
    return *reinterpret_cast<u32*>(&h);
}

__global__ void __launch_bounds__(THREADS, 2)
sfnn_r9_kernel(const float* __restrict__ x,
               const float* __restrict__ W1, const float* __restrict__ b1,
               const float* __restrict__ W2, const float* __restrict__ b2,
               const float* __restrict__ Wo, const float* __restrict__ tau_m,
               const float* __restrict__ tau_n1, const float* __restrict__ tau_n2) {
    extern __shared__ __align__(16) float sm[];
    float* dotsm = sm;                                   // 2*DOTW words
    float* ysm   = sm + 2 * DOTW;                        // 2*YTOT words
    __half* xsm  = reinterpret_cast<__half*>(sm + 2 * DOTW + 2 * YTOT);

    const int tid  = threadIdx.x;
    const int lane = tid & 31;
    const int wid  = tid >> 5;
    const int b    = blockIdx.x & (B_SZ - 1);
    const int half = blockIdx.x >> 7;
    const int hb   = half * HB;

    const float* xg = x + (size_t)b * T_SZ * DIN;
    const u32 xbase = smem_u32(xsm);
    float* gp = g_part + ((size_t)half * B_SZ + b) * T_SZ;

    // ---- recurrence constants for global channel h = hb + tid ----
    const int h = hb + tid;
    const float b1v = sigf(tau_n1[h]), b2v = sigf(tau_n2[h]), av = sigf(tau_m[h]);
    const u64 Bp  = pkf(b1v, b2v);
    const u64 Gp  = pkf(1.f - b1v, 1.f - b2v);
    const u64 GBp = pkf((1.f - b1v) * b1[h], (1.f - b2v) * b2[h]);
    const float amg = 1.f - av;
    const float wo  = Wo[h];

    // ---- W fragments permanent in registers ----
    const int wbr = wid >> 2;                   // warp's branch (0/1)
    const int wb  = (wid & 3) * 64;             // warp's local channel base
    u32 BF[8][2][2];
    {
        const float* Ws = wbr ? W2 : W1;
        const int chl = lane >> 2;
        const int kg  = 2 * (lane & 3);
#pragma unroll
        for (int nt = 0; nt < 8; nt++) {
            const int ch = hb + wb + nt * 8 + chl;      // global channel
#pragma unroll
            for (int kt = 0; kt < 2; kt++) {
                const int k0 = kt * 16 + kg;
                const float v0 = (k0     < KHALF) ? Ws[ch * KHALF + k0    ] : 0.f;
                const float v1 = (k0 + 1 < KHALF) ? Ws[ch * KHALF + k0 + 1] : 0.f;
                const float v2 = (k0 + 8 < KHALF) ? Ws[ch * KHALF + k0 + 8] : 0.f;
                const float v3 = (k0 + 9 < KHALF) ? Ws[ch * KHALF + k0 + 9] : 0.f;
                BF[nt][kt][0] = packh(v0, v1);
                BF[nt][kt][1] = packh(v2, v3);
            }
        }
    }

    // ---- x slot decomposition: 4 slots (of 1024) per thread per stage ----
    int xh_[4], gi_[4]; bool ok_[4];
#pragma unroll
    for (int i = 0; i < 4; i++) {
        const int sl = tid + i * 256;
        const int t  = sl >> 6, kk = sl & 63, br = kk >> 5, k = kk & 31;
        xh_[i] = t * 64 + kk;
        ok_[i] = (k < KHALF);
        gi_[i] = t * DIN + br * KHALF + k;
    }

    // lane constants for MMA dot store
    const int tlo  = lane >> 2;
    const int tc0  = tlo >> 2;
    const int toff = tlo & 3;
    const int chl2 = 2 * (lane & 3);

    auto mma_stage = [&](int s) {
        const int buf = s & 1;
        u32 A[2][4];
#pragma unroll
        for (int kt = 0; kt < 2; kt++) {
            const u32 addr = xbase + (u32)buf * (XWH * 2)
                           + (u32)(lane & 15) * 128
                           + (u32)(wbr * 32 + kt * 16 + ((lane >> 4) << 3)) * 2;
            ldmat4(A[kt], addr);
        }
        const int dB = buf * DOTW + wbr * BRW;
#pragma unroll
        for (int nt = 0; nt < 8; nt++) {
            float d0 = 0.f, d1 = 0.f, d2 = 0.f, d3 = 0.f;
            mma16816(d0, d1, d2, d3, A[0], BF[nt][0][0], BF[nt][0][1]);
            mma16816(d0, d1, d2, d3, A[1], BF[nt][1][0], BF[nt][1][1]);
            const int ch = wb + nt * 8 + chl2;          // local channel
            const int w0 = dB + tc0 * TCW + ch * 4 + toff;
            dotsm[w0]               = d0;   // (t=tlo,   ch)
            dotsm[w0 + 4]           = d1;   // (t=tlo,   ch+1)
            dotsm[w0 + 2 * TCW]     = d2;   // (t=tlo+8, ch)
            dotsm[w0 + 2 * TCW + 4] = d3;   // (t=tlo+8, ch+1)
        }
    };

    auto ysum = [&](int s) {
        const float* yb = ysm + (s & 1) * YTOT;
#pragma unroll
        for (int tt = 0; tt < 2; tt++) {
            const int t = wid * 2 + tt;
            const float4* yr = reinterpret_cast<const float4*>(yb + t * YW);
            const float4 q0 = yr[lane];
            const float4 q1 = yr[lane + 32];
            float acc = ((q0.x + q0.y) + (q0.z + q0.w))
                      + ((q1.x + q1.y) + (q1.z + q1.w));
#pragma unroll
            for (int off = 16; off; off >>= 1)
                acc += __shfl_xor_sync(0xFFFFFFFFu, acc, off);
            if (lane == 0) gp[s * ST + t] = acc;        // raw partial
        }
    };

    u64 d12 = 0ull;
    float mem = 0.f;

    // ---- prolog: stage x(0), x(1); prefetch x(2); first MMA ----
#pragma unroll
    for (int ss = 0; ss < 2; ss++) {
#pragma unroll
        for (int i = 0; i < 4; i++) {
            const float v = ok_[i] ? xg[ss * (ST * DIN) + gi_[i]] : 0.f;
            xsm[ss * XWH + xh_[i]] = __float2half_rn(v);
        }
    }
    float xv[4];
#pragma unroll
    for (int i = 0; i < 4; i++)
        xv[i] = ok_[i] ? xg[2 * (ST * DIN) + gi_[i]] : 0.f;
    __syncthreads();
    mma_stage(0);

    // ---- main loop: ONE barrier per stage ----
    for (int s = 0; s < NSTAGES; s++) {
        __syncthreads();   // dots(s), y(s-1), xbuf(s+1) visible

        if (s > 0) ysum(s - 1);
        if (s + 1 < NSTAGES) mma_stage(s + 1);

        // recurrence(s): reads dot buffer s&1, writes y buffer s&1
        {
            const int dB = (s & 1) * DOTW;
            float* yb = ysm + (s & 1) * YTOT;
            const int ch4 = tid * 4;
#pragma unroll
            for (int tc = 0; tc < 4; tc++) {
                const float4 i1 = *reinterpret_cast<const float4*>(
                    dotsm + dB + tc * TCW + ch4);
                const float4 i2 = *reinterpret_cast<const float4*>(
                    dotsm + dB + BRW + tc * TCW + ch4);
                const float i1a[4] = {i1.x, i1.y, i1.z, i1.w};
                const float i2a[4] = {i2.x, i2.y, i2.z, i2.w};
#pragma unroll
                for (int j = 0; j < 4; j++) {
                    d12 = fma2(Bp, d12, fma2(Gp, pkf(i1a[j], i2a[j]), GBp));
                    const float2 dd = unpk(d12);
                    mem = __fmaf_rn(av, mem, amg * (dd.x + dd.y));
                    yb[(tc * 4 + j) * YW + tid] = wo * mem;
                }
            }
        }

        // stage x(s+2) from prefetch regs; prefetch x(s+3)
        if (s + 2 < NSTAGES) {
            __half* xb = xsm + (s & 1) * XWH;   // (s+2)&1 == s&1
#pragma unroll
            for (int i = 0; i < 4; i++)
                xb[xh_[i]] = __float2half_rn(xv[i]);
            if (s + 3 < NSTAGES) {
                const size_t gb = (size_t)(s + 3) * (ST * DIN);
#pragma unroll
                for (int i = 0; i < 4; i++)
                    xv[i] = ok_[i] ? xg[gb + gi_[i]] : 0.f;
            }
        }
    }

    __syncthreads();
    ysum(NSTAGES - 1);
}

__global__ void sfnn_r9_epilogue(const float* __restrict__ bo,
                                 float* __restrict__ out) {
    const int i = blockIdx.x * blockDim.x + threadIdx.x;
    if (i < B_SZ * T_SZ) {
        const float v = g_part[i] + g_part[B_SZ * T_SZ + i] + bo[0];
        out[i] = 1.f / (1.f + __expf(-v));
    }
}

}  // namespace

extern "C" void kernel_launch(void* const* d_in, const int* in_sizes, int n_in,
                              void* d_out, int out_size) {
    const float* x      = (const float*)d_in[0];
    const float* W1     = (const float*)d_in[1];
    const float* b1     = (const float*)d_in[2];
    const float* W2     = (const float*)d_in[3];
    const float* b2     = (const float*)d_in[4];
    const float* Wo     = (const float*)d_in[5];
    const float* bo     = (const float*)d_in[6];
    const float* tau_m  = (const float*)d_in[7];
    const float* tau_n1 = (const float*)d_in[8];
    const float* tau_n2 = (const float*)d_in[9];
    float* out = (float*)d_out;

    cudaFuncSetAttribute(sfnn_r9_kernel,
                         cudaFuncAttributeMaxDynamicSharedMemorySize, SMEM_BYTES);
    sfnn_r9_kernel<<<2 * B_SZ, THREADS, SMEM_BYTES>>>(x, W1, b1, W2, b2, Wo,
                                                      tau_m, tau_n1, tau_n2);
    sfnn_r9_epilogue<<<(B_SZ * T_SZ + 511) / 512, 512>>>(bo, out);
}

// round 14
// speedup vs baseline: 2.4672x; 1.0206x over previous
#include <cuda_runtime.h>
#include <cuda_fp16.h>
#include <cstdint>

// TwoBranchDH_SFNN, R10: 4-way channel split (grid 512, 4 CTAs/SM) + fp16
// dot bounce with (t,t+8) half2 packing (1 STS.64 per n-tile fragment).
// CTA = 128 channels of one batch, 128 threads (4 warps), combined roles:
//   MMA: warp w: branch w>>1, 64-ch slice (w&1)*64; ldmatrix+HMMA+STS.64
//   recurrence: thread <-> channel (hb+tid), (d1,d2) packed in fma.rn.f32x2
//   ysum: 4 t/warp partial sums -> g_part scratch; epilogue adds 4 quarters.
// One __syncthreads per 16-t stage; dots / y / x double-buffered (~38KB smem).

namespace {

constexpr int B_SZ  = 128;
constexpr int T_SZ  = 2048;
constexpr int DIN   = 40;
constexpr int KHALF = 20;
constexpr int QB      = 128;            // channels per block
constexpr int THREADS = 128;
constexpr int ST      = 16;             // timesteps per stage
constexpr int NSTAGES = T_SZ / ST;      // 128

// smem geometry (32-bit words)
constexpr int RW   = 136;               // dot row stride (128 ch-words + pad, ≡8 mod 32)
constexpr int BRH  = 8 * RW;            // per-branch block (8 tlo rows) = 1088
constexpr int DOTH = 2 * BRH;           // both branches, one buffer = 2176
constexpr int YW   = 132;               // y row stride (128 + pad)
constexpr int YTOT = ST * YW;           // one y buffer = 2112
constexpr int XWH  = ST * 64;           // halves per x buffer = 1024
constexpr int SMEM_WORDS = 2 * DOTH + 2 * YTOT + (2 * XWH) / 2;  // 9600
constexpr int SMEM_BYTES = SMEM_WORDS * 4;                       // 38400

typedef unsigned long long u64;
typedef uint32_t u32;

__device__ float g_part[4 * B_SZ * T_SZ];   // partial channel sums (4 MB)

__device__ __forceinline__ u32 smem_u32(const void* p) {
    u32 a;
    asm("{ .reg .u64 t; cvta.to.shared.u64 t, %1; cvt.u32.u64 %0, t; }"
        : "=r"(a) : "l"(p));
    return a;
}
__device__ __forceinline__ u64 pkf(float lo, float hi) {
    u64 r; asm("mov.b64 %0, {%1, %2};" : "=l"(r) : "f"(lo), "f"(hi)); return r;
}
__device__ __forceinline__ float2 unpk(u64 v) {
    float2 r; asm("mov.b64 {%0, %1}, %2;" : "=f"(r.x), "=f"(r.y) : "l"(v)); return r;
}
__device__ __forceinline__ u64 fma2(u64 a, u64 b, u64 c) {
    u64 d; asm("fma.rn.f32x2 %0, %1, %2, %3;" : "=l"(d) : "l"(a), "l"(b), "l"(c)); return d;
}

__device__ __forceinline__ void ldmat4(u32* r, u32 addr) {
    asm volatile("ldmatrix.sync.aligned.m8n8.x4.shared.b16 {%0,%1,%2,%3}, [%4];"
                 : "=r"(r[0]), "=r"(r[1]), "=r"(r[2]), "=r"(r[3]) : "r"(addr));
}
__device__ __forceinline__ void mma16816(float& d0, float& d1, float& d2, float& d3,
                                         const u32* a, u32 b0, u32 b1) {
    asm volatile("mma.sync.aligned.m16n8k16.row.col.f32.f16.f16.f32 "
                 "{%0,%1,%2,%3}, {%4,%5,%6,%7}, {%8,%9}, {%0,%1,%2,%3};"
                 : "+f"(d0), "+f"(d1), "+f"(d2), "+f"(d3)
                 : "r"(a[0]), "r"(a[1]), "r"(a[2]), "r"(a[3]), "r"(b0), "r"(b1));
}
__device__ __forceinline__ float sigf(float v) { return 1.0f / (1.0f + expf(-v)); }
__device__ __forceinline__ u32 packh(float a, float b) {
    __half2 h = __floats2half2_rn(a, b);
    return *reinterpret_cast<u32*>(&h);
}

__global__ void __launch_bounds__(THREADS, 4)
sfnn_r10_kernel(const float* __restrict__ x,
                const float* __restrict__ W1, const float* __restrict__ b1,
                const float* __restrict__ W2, const float* __restrict__ b2,
                const float* __restrict__ Wo, const float* __restrict__ tau_m,
                const float* __restrict__ tau_n1, const float* __restrict__ tau_n2) {
    extern __shared__ __align__(16) u32 smw[];
    u32*   dotw = smw;                                   // 2*DOTH words (fp16 half2)
    float* ysm  = reinterpret_cast<float*>(smw + 2 * DOTH);   // 2*YTOT words
    __half* xsm = reinterpret_cast<__half*>(smw + 2 * DOTH + 2 * YTOT);

    const int tid  = threadIdx.x;
    const int lane = tid & 31;
    const int wid  = tid >> 5;                  // 0..3
    const int b    = blockIdx.x & (B_SZ - 1);
    const int q    = blockIdx.x >> 7;           // quarter 0..3
    const int hb   = q * QB;

    const float* xg = x + (size_t)b * T_SZ * DIN;
    const u32 xbase = smem_u32(xsm);
    float* gp = g_part + ((size_t)q * B_SZ + b) * T_SZ;

    // ---- recurrence constants for global channel h = hb + tid ----
    const int h = hb + tid;
    const float b1v = sigf(tau_n1[h]), b2v = sigf(tau_n2[h]), av = sigf(tau_m[h]);
    const u64 Bp  = pkf(b1v, b2v);
    const u64 Gp  = pkf(1.f - b1v, 1.f - b2v);
    const u64 GBp = pkf((1.f - b1v) * b1[h], (1.f - b2v) * b2[h]);
    const float amg = 1.f - av;
    const float wo  = Wo[h];

    // ---- W fragments permanent in registers ----
    const int wbr = wid >> 1;                   // warp's branch (0/1)
    const int wb  = (wid & 1) * 64;             // warp's local channel base
    u32 BF[8][2][2];
    {
        const float* Ws = wbr ? W2 : W1;
        const int chl = lane >> 2;
        const int kg  = 2 * (lane & 3);
#pragma unroll
        for (int nt = 0; nt < 8; nt++) {
            const int ch = hb + wb + nt * 8 + chl;      // global channel
#pragma unroll
            for (int kt = 0; kt < 2; kt++) {
                const int k0 = kt * 16 + kg;
                const float v0 = (k0     < KHALF) ? Ws[ch * KHALF + k0    ] : 0.f;
                const float v1 = (k0 + 1 < KHALF) ? Ws[ch * KHALF + k0 + 1] : 0.f;
                const float v2 = (k0 + 8 < KHALF) ? Ws[ch * KHALF + k0 + 8] : 0.f;
                const float v3 = (k0 + 9 < KHALF) ? Ws[ch * KHALF + k0 + 9] : 0.f;
                BF[nt][kt][0] = packh(v0, v1);
                BF[nt][kt][1] = packh(v2, v3);
            }
        }
    }

    // ---- x staging: 1024 slots, 128 threads -> 8 slots each ----
    const int xkk  = tid & 63;                  // kk is shared across slots
    const int xt0  = tid >> 6;                  // base t (0/1), slots t = xt0 + 2i
    const int xbr  = xkk >> 5;
    const int xk   = xkk & 31;
    const bool xok = (xk < KHALF);
    const int xgc  = xbr * KHALF + xk;          // column in x row

    auto stage_x = [&](int s) {
        const int buf = s & 1;
        const float* xs = xg + (size_t)s * (ST * DIN);
        __half* xb = xsm + buf * XWH;
#pragma unroll
        for (int i = 0; i < 8; i++) {
            const int t = xt0 + 2 * i;
            const float v = xok ? xs[t * DIN + xgc] : 0.f;
            xb[t * 64 + xkk] = __float2half_rn(v);
        }
    };

    // lane constants for dot store
    const int tlo  = lane >> 2;                 // 0..7
    const int chl2 = 2 * (lane & 3);

    auto mma_stage = [&](int s) {
        const int buf = s & 1;
        u32 A[2][4];
#pragma unroll
        for (int kt = 0; kt < 2; kt++) {
            const u32 addr = xbase + (u32)buf * (XWH * 2)
                           + (u32)(lane & 15) * 128
                           + (u32)(wbr * 32 + kt * 16 + ((lane >> 4) << 3)) * 2;
            ldmat4(A[kt], addr);
        }
        u32* dB = dotw + buf * DOTH + wbr * BRH + tlo * RW;
#pragma unroll
        for (int nt = 0; nt < 8; nt++) {
            float d0 = 0.f, d1 = 0.f, d2 = 0.f, d3 = 0.f;
            mma16816(d0, d1, d2, d3, A[0], BF[nt][0][0], BF[nt][0][1]);
            mma16816(d0, d1, d2, d3, A[1], BF[nt][1][0], BF[nt][1][1]);
            // half2 packing over (t, t+8): h02 = ch@(t,t+8), h13 = (ch+1)@(t,t+8)
            const u32 h02 = packh(d0, d2);
            const u32 h13 = packh(d1, d3);
            *reinterpret_cast<uint2*>(dB + wb + nt * 8 + chl2) =
                make_uint2(h02, h13);
        }
    };

    auto ysum = [&](int s) {
        const float* yb = ysm + (s & 1) * YTOT;
#pragma unroll
        for (int tt = 0; tt < 4; tt++) {
            const int t = wid * 4 + tt;
            const float4 v = *reinterpret_cast<const float4*>(yb + t * YW + lane * 4);
            float acc = (v.x + v.y) + (v.z + v.w);
#pragma unroll
            for (int off = 16; off; off >>= 1)
                acc += __shfl_xor_sync(0xFFFFFFFFu, acc, off);
            if (lane == 0) gp[s * ST + t] = acc;        // raw partial
        }
    };

    u64 d12 = 0ull;
    float mem = 0.f;

    // ---- prolog ----
    stage_x(0);
    stage_x(1);
    __syncthreads();
    mma_stage(0);

    // ---- main loop: ONE barrier per stage ----
    for (int s = 0; s < NSTAGES; s++) {
        __syncthreads();   // dots(s), y(s-1), xbuf(s+1) visible

        if (s > 0) ysum(s - 1);
        if (s + 1 < NSTAGES) mma_stage(s + 1);

        // recurrence(s): reads fp16 dot buffer s&1, writes fp32 y buffer s&1
        {
            const u32* dB = dotw + (s & 1) * DOTH;
            float* yb = ysm + (s & 1) * YTOT;
            float2 f1[8], f2[8];
#pragma unroll
            for (int r = 0; r < 8; r++) {
                const u32 w1 = dB[r * RW + tid];            // branch 1: ch@(t=r, t=r+8)
                const u32 w2 = dB[BRH + r * RW + tid];      // branch 2
                f1[r] = __half22float2(*reinterpret_cast<const __half2*>(&w1));
                f2[r] = __half22float2(*reinterpret_cast<const __half2*>(&w2));
            }
#pragma unroll
            for (int t = 0; t < 8; t++) {
                d12 = fma2(Bp, d12, fma2(Gp, pkf(f1[t].x, f2[t].x), GBp));
                const float2 dd = unpk(d12);
                mem = __fmaf_rn(av, mem, amg * (dd.x + dd.y));
                yb[t * YW + tid] = wo * mem;
            }
#pragma unroll
            for (int t = 0; t < 8; t++) {
                d12 = fma2(Bp, d12, fma2(Gp, pkf(f1[t].y, f2[t].y), GBp));
                const float2 dd = unpk(d12);
                mem = __fmaf_rn(av, mem, amg * (dd.x + dd.y));
                yb[(t + 8) * YW + tid] = wo * mem;
            }
        }

        if (s + 2 < NSTAGES) stage_x(s + 2);
    }

    __syncthreads();
    ysum(NSTAGES - 1);
}

__global__ void sfnn_r10_epilogue(const float* __restrict__ bo,
                                  float* __restrict__ out) {
    const int i = blockIdx.x * blockDim.x + threadIdx.x;
    if (i < B_SZ * T_SZ) {
        const int N = B_SZ * T_SZ;
        const float v = g_part[i] + g_part[N + i] + g_part[2 * N + i]
                      + g_part[3 * N + i] + bo[0];
        out[i] = 1.f / (1.f + __expf(-v));
    }
}

}  // namespace

extern "C" void kernel_launch(void* const* d_in, const int* in_sizes, int n_in,
                              void* d_out, int out_size) {
    const float* x      = (const float*)d_in[0];
    const float* W1     = (const float*)d_in[1];
    const float* b1     = (const float*)d_in[2];
    const float* W2     = (const float*)d_in[3];
    const float* b2     = (const float*)d_in[4];
    const float* Wo     = (const float*)d_in[5];
    const float* bo     = (const float*)d_in[6];
    const float* tau_m  = (const float*)d_in[7];
    const float* tau_n1 = (const float*)d_in[8];
    const float* tau_n2 = (const float*)d_in[9];
    float* out = (float*)d_out;

    cudaFuncSetAttribute(sfnn_r10_kernel,
                         cudaFuncAttributeMaxDynamicSharedMemorySize, SMEM_BYTES);
    sfnn_r10_kernel<<<4 * B_SZ, THREADS, SMEM_BYTES>>>(x, W1, b1, W2, b2, Wo,
                                                       tau_m, tau_n1, tau_n2);
    sfnn_r10_epilogue<<<(B_SZ * T_SZ + 511) / 512, 512>>>(bo, out);
}